// round 13
// baseline (speedup 1.0000x reference)
#include <cuda_runtime.h>

// Problem: seq [1, 8192, 4096] fp32, n = 64.
// out = [col-mean over rows (4096), softmax-value histogram (64)] -> 4160 fp32.
//
// Key insight (R12-confirmed): the reference's segment_sum accumulates each
// bin in a single serial fp32 accumulator. For the big low bins the
// accumulator's ulp becomes comparable to (or larger than) the addends, so
// round-to-nearest systematically deviates from the exact sum by hundreds of
// units. We must REPLAY that serial fp32 accumulation, not compute the exact
// sum. Within a regime A in [2^e, 2^{e+1}) the serial update is
// A += u*round(p/u), u = 2^(e-23) -- order-independent -- so per-chunk
// integer sums at each scale + a short serial walk over 1024 chunks
// reproduce the trajectory. Bins 0..3 need this; bins >= 4 have addend/ulp
// ratios > 13 and are unbiased (exact reduction suffices).

namespace {
constexpr int R      = 8192;
constexpr int C      = 4096;
constexpr int NBINS  = 64;
constexpr int TCOLS  = 256;
constexpr int TROWS  = 128;
constexpr int SLABS  = C / TCOLS;        // 16
constexpr int RTILES = R / TROWS;        // 64
constexpr int NHB    = SLABS * RTILES;   // 1024 chunks
constexpr int NEMU   = 4;                // bins emulated serially
}

// Scratch (device allocation forbidden -> __device__ globals)
__device__ float    g_rowM[R];
__device__ float    g_rowInv[R];              // 1/S (rcp_rn)
__device__ unsigned g_mnBits, g_mxBits;
__device__ float    g_colPart[RTILES][C];
__device__ float    g_histPart[NHB][NBINS];   // bins 4..63 used
// Serial-accumulation emulation tables (bins 0..3), per chunk:
//   g_bf[b]    : exact chunk sum                (regime A < 256)
//   g_bi[b][k] : sum of round(p * 2^(15-k))     (regimes [256,512), [512,1024),
//                [1024,2048), [2048,4096), [4096,8192) for k = 0..4)
__device__ float    g_bf[NEMU][NHB];
__device__ int      g_bi[NEMU][NHB][5];

// ---------------------------------------------------------------------------
// Accurate exp (~2 ulp), flag-independent, deterministic. exp_acc(0) == 1.
// ---------------------------------------------------------------------------
__device__ __forceinline__ float exp_acc(float x) {
    float t = fmaf(x, 1.442695041f, 12582912.0f);
    float n = t - 12582912.0f;
    float r = fmaf(n, -0.693359375f,    x);
    r       = fmaf(n,  2.12194440e-4f,  r);
    float p =           1.9875691500e-4f;
    p = fmaf(p, r,      1.3981999507e-3f);
    p = fmaf(p, r,      8.3334519073e-3f);
    p = fmaf(p, r,      4.1665795894e-2f);
    p = fmaf(p, r,      1.6666665459e-1f);
    p = fmaf(p, r,      5.0000001201e-1f);
    float e = fmaf(r, fmaf(r, p, 1.0f), 1.0f);
    int   ni = (int)n;
    float s = (ni < -126) ? 0.0f : __int_as_float((ni + 127) << 23);
    return e * s;
}

// ---------------------------------------------------------------------------
__global__ void initK() {
    g_mnBits = 0x7f800000u;   // +inf
    g_mxBits = 0u;
}

// ---------------------------------------------------------------------------
// Kernel 1: one block per row -> M, inv = rcp(S), numeric p-extrema using
// the bit-identical expression histColK evaluates (p = e * inv).
// ---------------------------------------------------------------------------
__global__ __launch_bounds__(256) void rowK(const float* __restrict__ x) {
    const int row  = blockIdx.x;
    const int tid  = threadIdx.x;
    const int lane = tid & 31;
    const int warp = tid >> 5;

    const float4* p4 = reinterpret_cast<const float4*>(x + (size_t)row * C);
    float4 v[4];
    #pragma unroll
    for (int i = 0; i < 4; i++) v[i] = __ldg(p4 + i * 256 + tid);

    float mx = -__int_as_float(0x7f800000);
    #pragma unroll
    for (int i = 0; i < 4; i++)
        mx = fmaxf(mx, fmaxf(fmaxf(v[i].x, v[i].y), fmaxf(v[i].z, v[i].w)));
    #pragma unroll
    for (int o = 16; o > 0; o >>= 1)
        mx = fmaxf(mx, __shfl_xor_sync(0xffffffffu, mx, o));

    __shared__ float sA[8], sB[8], sC[8];
    if (lane == 0) sA[warp] = mx;
    __syncthreads();
    float M = sA[0];
    #pragma unroll
    for (int w = 1; w < 8; w++) M = fmaxf(M, sA[w]);
    __syncthreads();

    float s = 0.0f;
    float emax = -__int_as_float(0x7f800000);
    float emin =  __int_as_float(0x7f800000);
    float vv[16] = {v[0].x, v[0].y, v[0].z, v[0].w,  v[1].x, v[1].y, v[1].z, v[1].w,
                    v[2].x, v[2].y, v[2].z, v[2].w,  v[3].x, v[3].y, v[3].z, v[3].w};
    #pragma unroll
    for (int i = 0; i < 16; i++) {
        float e = exp_acc(vv[i] - M);
        s += e;
        emax = fmaxf(emax, e);
        emin = fminf(emin, e);
    }
    #pragma unroll
    for (int o = 16; o > 0; o >>= 1) {
        s    += __shfl_xor_sync(0xffffffffu, s, o);
        emax  = fmaxf(emax, __shfl_xor_sync(0xffffffffu, emax, o));
        emin  = fminf(emin, __shfl_xor_sync(0xffffffffu, emin, o));
    }
    if (lane == 0) { sA[warp] = s; sB[warp] = emax; sC[warp] = emin; }
    __syncthreads();

    if (tid == 0) {
        float S = sA[0];
        float EX = sB[0], EN = sC[0];
        #pragma unroll
        for (int w = 1; w < 8; w++) {
            S += sA[w];                        // fixed order
            EX = fmaxf(EX, sB[w]);
            EN = fminf(EN, sC[w]);
        }
        float inv = __frcp_rn(S);
        g_rowM[row]   = M;
        g_rowInv[row] = inv;
        // Monotone: max/min over elements of fl(e*inv) == fl(EX*inv)/fl(EN*inv)
        float pmax = EX * inv;
        float pmin = EN * inv;
        atomicMax(&g_mxBits, __float_as_uint(pmax));
        atomicMin(&g_mnBits, __float_as_uint(pmin));
    }
}

// ---------------------------------------------------------------------------
// Kernel 2: binning + column partials. Bins 0..3 record (exact float sum,
// 5 multi-scale rounded integer sums) per chunk for the serial replay.
// Bins 4..63 exact via smem atomics (sparse). idx==64 (global max) dropped.
// ---------------------------------------------------------------------------
__global__ __launch_bounds__(256) void histColK(const float* __restrict__ x) {
    const float mnv  = __uint_as_float(g_mnBits);
    const float mxv  = __uint_as_float(g_mxBits);
    const float dd   = (mxv - mnv) * 0.015625f;   // /64 exact
    const float invD = __frcp_rn(dd);

    __shared__ float sh[NBINS];
    __shared__ float scolW[8][TCOLS];
    __shared__ float sFw[8][NEMU];
    __shared__ int   sIw[8][NEMU][5];
    if (threadIdx.x < NBINS) sh[threadIdx.x] = 0.0f;
    #pragma unroll
    for (int w = 0; w < 8; w++) scolW[w][threadIdx.x] = 0.0f;
    __syncthreads();

    const int slab    = blockIdx.x;
    const int tile    = blockIdx.y;
    const int rowBase = tile * TROWS;
    const int warp    = threadIdx.x >> 5;
    const int lane    = threadIdx.x & 31;
    const int colBase = slab * TCOLS;

    float cs[8] = {0.f, 0.f, 0.f, 0.f, 0.f, 0.f, 0.f, 0.f};
    float f0 = 0.f, f1 = 0.f, f2 = 0.f, f3 = 0.f;
    int c00=0,c01=0,c02=0,c03=0,c04=0;
    int c10=0,c11=0,c12=0,c13=0,c14=0;
    int c20=0,c21=0,c22=0,c23=0,c24=0;
    int c30=0,c31=0,c32=0,c33=0,c34=0;

    for (int r = warp; r < TROWS; r += 8) {
        const int   row = rowBase + r;
        const float M   = g_rowM[row];
        const float inv = g_rowInv[row];
        const float4* p4 =
            reinterpret_cast<const float4*>(x + (size_t)row * C + colBase);
        float4 a = __ldg(p4 + lane);
        float4 b = __ldg(p4 + 32 + lane);
        float v[8] = {a.x, a.y, a.z, a.w, b.x, b.y, b.z, b.w};
        #pragma unroll
        for (int k = 0; k < 8; k++) {
            float p = exp_acc(v[k] - M) * inv;
            float t = (p - mnv) * invD;
            int idx = __float2int_rd(t);              // t in [0, 64]
            if (idx < NEMU) {
                // uniform pre-compute of all scale-rounds (cheap, branchless)
                int r0 = __float2int_rn(p * 32768.0f); // u=2^-15, A in [256,512)
                int r1 = __float2int_rn(p * 16384.0f); // u=2^-14
                int r2 = __float2int_rn(p * 8192.0f);  // u=2^-13
                int r3 = __float2int_rn(p * 4096.0f);  // u=2^-12
                int r4 = __float2int_rn(p * 2048.0f);  // u=2^-11, A in [4096,8192)
                if (idx == 0) {
                    f0 += p; c00+=r0; c01+=r1; c02+=r2; c03+=r3; c04+=r4;
                } else if (idx == 1) {
                    f1 += p; c10+=r0; c11+=r1; c12+=r2; c13+=r3; c14+=r4;
                } else if (idx == 2) {
                    f2 += p; c20+=r0; c21+=r1; c22+=r2; c23+=r3; c24+=r4;
                } else {
                    f3 += p; c30+=r0; c31+=r1; c32+=r2; c33+=r3; c34+=r4;
                }
            } else if (idx < NBINS) {
                atomicAdd(&sh[idx], p);
            }                                         // idx == 64: dropped
        }
        cs[0] += a.x; cs[1] += a.y; cs[2] += a.z; cs[3] += a.w;
        cs[4] += b.x; cs[5] += b.y; cs[6] += b.z; cs[7] += b.w;
    }

    #pragma unroll
    for (int k = 0; k < 4; k++) {
        scolW[warp][4 * lane + k]       = cs[k];
        scolW[warp][128 + 4 * lane + k] = cs[4 + k];
    }
    // Butterfly-reduce all emulation counters within the warp
    #pragma unroll
    for (int o = 16; o > 0; o >>= 1) {
        f0 += __shfl_xor_sync(0xffffffffu, f0, o);
        f1 += __shfl_xor_sync(0xffffffffu, f1, o);
        f2 += __shfl_xor_sync(0xffffffffu, f2, o);
        f3 += __shfl_xor_sync(0xffffffffu, f3, o);
        c00 += __shfl_xor_sync(0xffffffffu, c00, o);
        c01 += __shfl_xor_sync(0xffffffffu, c01, o);
        c02 += __shfl_xor_sync(0xffffffffu, c02, o);
        c03 += __shfl_xor_sync(0xffffffffu, c03, o);
        c04 += __shfl_xor_sync(0xffffffffu, c04, o);
        c10 += __shfl_xor_sync(0xffffffffu, c10, o);
        c11 += __shfl_xor_sync(0xffffffffu, c11, o);
        c12 += __shfl_xor_sync(0xffffffffu, c12, o);
        c13 += __shfl_xor_sync(0xffffffffu, c13, o);
        c14 += __shfl_xor_sync(0xffffffffu, c14, o);
        c20 += __shfl_xor_sync(0xffffffffu, c20, o);
        c21 += __shfl_xor_sync(0xffffffffu, c21, o);
        c22 += __shfl_xor_sync(0xffffffffu, c22, o);
        c23 += __shfl_xor_sync(0xffffffffu, c23, o);
        c24 += __shfl_xor_sync(0xffffffffu, c24, o);
        c30 += __shfl_xor_sync(0xffffffffu, c30, o);
        c31 += __shfl_xor_sync(0xffffffffu, c31, o);
        c32 += __shfl_xor_sync(0xffffffffu, c32, o);
        c33 += __shfl_xor_sync(0xffffffffu, c33, o);
        c34 += __shfl_xor_sync(0xffffffffu, c34, o);
    }
    if (lane == 0) {
        sFw[warp][0] = f0; sFw[warp][1] = f1; sFw[warp][2] = f2; sFw[warp][3] = f3;
        sIw[warp][0][0]=c00; sIw[warp][0][1]=c01; sIw[warp][0][2]=c02; sIw[warp][0][3]=c03; sIw[warp][0][4]=c04;
        sIw[warp][1][0]=c10; sIw[warp][1][1]=c11; sIw[warp][1][2]=c12; sIw[warp][1][3]=c13; sIw[warp][1][4]=c14;
        sIw[warp][2][0]=c20; sIw[warp][2][1]=c21; sIw[warp][2][2]=c22; sIw[warp][2][3]=c23; sIw[warp][2][4]=c24;
        sIw[warp][3][0]=c30; sIw[warp][3][1]=c31; sIw[warp][3][2]=c32; sIw[warp][3][3]=c33; sIw[warp][3][4]=c34;
    }
    __syncthreads();

    float csum = 0.0f;
    #pragma unroll
    for (int w = 0; w < 8; w++) csum += scolW[w][threadIdx.x];
    g_colPart[tile][colBase + threadIdx.x] = csum;

    const int chunk = tile * SLABS + slab;
    if (threadIdx.x < NEMU) {                    // thread b finalizes bin b
        const int b = threadIdx.x;
        float F = 0.f; int I0=0, I1=0, I2=0, I3=0, I4=0;
        #pragma unroll
        for (int w = 0; w < 8; w++) {
            F += sFw[w][b];
            I0 += sIw[w][b][0]; I1 += sIw[w][b][1]; I2 += sIw[w][b][2];
            I3 += sIw[w][b][3]; I4 += sIw[w][b][4];
        }
        g_bf[b][chunk] = F;
        g_bi[b][chunk][0] = I0; g_bi[b][chunk][1] = I1; g_bi[b][chunk][2] = I2;
        g_bi[b][chunk][3] = I3; g_bi[b][chunk][4] = I4;
    }
    if (threadIdx.x >= NEMU && threadIdx.x < NBINS)
        g_histPart[chunk][threadIdx.x] = sh[threadIdx.x];
}

// ---------------------------------------------------------------------------
// Kernel 3: reduce hist partials for bins 4..63 (fixed tree)
// ---------------------------------------------------------------------------
__global__ __launch_bounds__(256) void histRedK(float* __restrict__ out) {
    const int bin = blockIdx.x + NEMU;           // bins 4..63
    float s = 0.0f;
    #pragma unroll
    for (int k = 0; k < NHB / 256; k++)
        s += g_histPart[threadIdx.x + k * 256][bin];
    __shared__ float sm[256];
    sm[threadIdx.x] = s;
    __syncthreads();
    #pragma unroll
    for (int st = 128; st > 0; st >>= 1) {
        if (threadIdx.x < st) sm[threadIdx.x] += sm[threadIdx.x + st];
        __syncthreads();
    }
    if (threadIdx.x == 0) out[C + bin] = sm[0];
}

// ---------------------------------------------------------------------------
// Kernel 4: replay the serial fp32 accumulation for bins 0..3 (warp b -> bin
// b). Within regime A in [2^e, 2^{e+1}) the adds are order-independent, so
// chunk-granular integer sums at the regime's scale suffice.
// ---------------------------------------------------------------------------
__global__ void finalizeK(float* __restrict__ out) {
    const int w    = threadIdx.x >> 5;
    const int lane = threadIdx.x & 31;
    if (w >= NEMU) return;
    double A = 0.0;
    for (int b = 0; b < NHB / 32; b++) {
        const int c = b * 32 + lane;
        float fF = g_bf[w][c];
        int j0 = g_bi[w][c][0], j1 = g_bi[w][c][1], j2 = g_bi[w][c][2];
        int j3 = g_bi[w][c][3], j4 = g_bi[w][c][4];
        #pragma unroll
        for (int l = 0; l < 32; l++) {
            float ff = __shfl_sync(0xffffffffu, fF, l);
            int k0 = __shfl_sync(0xffffffffu, j0, l);
            int k1 = __shfl_sync(0xffffffffu, j1, l);
            int k2 = __shfl_sync(0xffffffffu, j2, l);
            int k3 = __shfl_sync(0xffffffffu, j3, l);
            int k4 = __shfl_sync(0xffffffffu, j4, l);
            if      (A < 256.0)  A += (double)ff;
            else if (A < 512.0)  A += (double)k0 * (1.0 / 32768.0);
            else if (A < 1024.0) A += (double)k1 * (1.0 / 16384.0);
            else if (A < 2048.0) A += (double)k2 * (1.0 / 8192.0);
            else if (A < 4096.0) A += (double)k3 * (1.0 / 4096.0);
            else                 A += (double)k4 * (1.0 / 2048.0);
        }
    }
    if (lane == 0) out[C + w] = (float)A;
}

// ---------------------------------------------------------------------------
// Kernel 5: column means from 64 tile partials (fixed order), exact /8192
// ---------------------------------------------------------------------------
__global__ __launch_bounds__(256) void meanK(float* __restrict__ out) {
    const int c = blockIdx.x * 256 + threadIdx.x;
    float s = 0.0f;
    #pragma unroll
    for (int t = 0; t < RTILES; t++) s += g_colPart[t][c];
    out[c] = s * (1.0f / 8192.0f);
}

// ---------------------------------------------------------------------------
extern "C" void kernel_launch(void* const* d_in, const int* in_sizes, int n_in,
                              void* d_out, int out_size) {
    const float* x   = (const float*)d_in[0];   // seq [1, 8192, 4096]
    float*       out = (float*)d_out;           // [4160]

    initK    <<<1, 1>>>();
    rowK     <<<R, 256>>>(x);
    histColK <<<dim3(SLABS, RTILES), 256>>>(x);
    histRedK <<<NBINS - NEMU, 256>>>(out);
    finalizeK<<<1, NEMU * 32>>>(out);
    meanK    <<<C / 256, 256>>>(out);
}

// round 17
// speedup vs baseline: 1.6760x; 1.6760x over previous
#include <cuda_runtime.h>

// Problem: seq [1, 8192, 4096] fp32, n = 64.
// out = [col-mean over rows (4096), softmax-value histogram (64)] -> 4160 fp32.
//
// R12/R13-confirmed key insight: the reference's segment_sum accumulates each
// bin in a single serial fp32 accumulator; for the big low bins the
// accumulator's ulp rivals the addends, so RN deviates from the exact sum by
// hundreds of units. We REPLAY that serial fp32 accumulation for bins 0..3
// (regime-wise order-independence -> per-chunk integer sums at 5 scales +
// a 1024-step serial walk). Bins >= 4 are unbiased; exact reduction.

namespace {
constexpr int R      = 8192;
constexpr int C      = 4096;
constexpr int NBINS  = 64;
constexpr int TCOLS  = 256;
constexpr int TROWS  = 128;
constexpr int SLABS  = C / TCOLS;        // 16
constexpr int RTILES = R / TROWS;        // 64
constexpr int NHB    = SLABS * RTILES;   // 1024 chunks
constexpr int NEMU   = 4;                // serially-replayed bins
constexpr int NREG   = 8;                // register-accumulated bins (0..7)
}

__device__ float    g_rowM[R];
__device__ float    g_rowInv[R];              // 1/S
__device__ unsigned g_mnBits, g_mxBits;
__device__ float    g_colPart[RTILES][C];
__device__ float    g_histPart[NHB][NBINS];   // bins 4..63 used
// Serial-replay tables (bins 0..3), per chunk:
//  g_bf[b]    : exact chunk sum            (regime A < 256)
//  g_bi[b][k] : sum of round(p * 2^(15-k)) (regimes [256,512),[512,1024),
//               [1024,2048),[2048,4096),[4096,8192), k = 0..4)
__device__ float    g_bf[NEMU][NHB];
__device__ int      g_bi[NEMU][NHB][5];

// ---------------------------------------------------------------------------
__global__ void initK() {
    g_mnBits = 0x7f800000u;   // +inf
    g_mxBits = 0u;
}

// ---------------------------------------------------------------------------
// Kernel 1: one block per row -> M, inv = rcp(S), p-extrema.
// __expf(0) == 1 exactly, so the row's max element has p = inv; min element
// p = __expf(rmn - M) * inv (same expression histColK evaluates).
// ---------------------------------------------------------------------------
__global__ __launch_bounds__(256) void rowK(const float* __restrict__ x) {
    const int row  = blockIdx.x;
    const int tid  = threadIdx.x;
    const int lane = tid & 31;
    const int warp = tid >> 5;

    const float4* p4 = reinterpret_cast<const float4*>(x + (size_t)row * C);
    float4 v[4];
    #pragma unroll
    for (int i = 0; i < 4; i++) v[i] = __ldg(p4 + i * 256 + tid);

    float mx = -__int_as_float(0x7f800000), mn = __int_as_float(0x7f800000);
    #pragma unroll
    for (int i = 0; i < 4; i++) {
        mx = fmaxf(mx, fmaxf(fmaxf(v[i].x, v[i].y), fmaxf(v[i].z, v[i].w)));
        mn = fminf(mn, fminf(fminf(v[i].x, v[i].y), fminf(v[i].z, v[i].w)));
    }
    #pragma unroll
    for (int o = 16; o > 0; o >>= 1) {
        mx = fmaxf(mx, __shfl_xor_sync(0xffffffffu, mx, o));
        mn = fminf(mn, __shfl_xor_sync(0xffffffffu, mn, o));
    }

    __shared__ float sA[8], sB[8];
    if (lane == 0) { sA[warp] = mx; sB[warp] = mn; }
    __syncthreads();
    float M = sA[0], rmn = sB[0];
    #pragma unroll
    for (int w = 1; w < 8; w++) {
        M   = fmaxf(M,   sA[w]);
        rmn = fminf(rmn, sB[w]);
    }
    __syncthreads();

    float s = 0.0f;
    #pragma unroll
    for (int i = 0; i < 4; i++) {
        s += __expf(v[i].x - M);
        s += __expf(v[i].y - M);
        s += __expf(v[i].z - M);
        s += __expf(v[i].w - M);
    }
    #pragma unroll
    for (int o = 16; o > 0; o >>= 1)
        s += __shfl_xor_sync(0xffffffffu, s, o);
    if (lane == 0) sA[warp] = s;
    __syncthreads();

    if (tid == 0) {
        float S = sA[0];
        #pragma unroll
        for (int w = 1; w < 8; w++) S += sA[w];   // fixed order
        float inv = __frcp_rn(S);
        g_rowM[row]   = M;
        g_rowInv[row] = inv;
        float pmax = inv;                          // __expf(0)*inv
        float pmin = __expf(rmn - M) * inv;
        atomicMax(&g_mxBits, __float_as_uint(pmax));
        atomicMin(&g_mnBits, __float_as_uint(pmin));
    }
}

// ---------------------------------------------------------------------------
// Kernel 2: binning + column partials. Bins 0..3 record serial-replay data;
// bins 4..7 in registers; bins 8..63 via smem atomics; idx>=64 dropped.
// ---------------------------------------------------------------------------
__global__ __launch_bounds__(256) void histColK(const float* __restrict__ x) {
    const float mnv  = __uint_as_float(g_mnBits);
    const float mxv  = __uint_as_float(g_mxBits);
    const float dd   = (mxv - mnv) * 0.015625f;   // /64 exact
    const float invD = __frcp_rn(dd);

    __shared__ float sh[NBINS];
    __shared__ float scolW[8][TCOLS];
    __shared__ float sFw[8][NREG];     // per-warp float sums, bins 0..7
    __shared__ int   sIw[8][NEMU][5];
    if (threadIdx.x < NBINS) sh[threadIdx.x] = 0.0f;
    #pragma unroll
    for (int w = 0; w < 8; w++) scolW[w][threadIdx.x] = 0.0f;
    __syncthreads();

    const int slab    = blockIdx.x;
    const int tile    = blockIdx.y;
    const int rowBase = tile * TROWS;
    const int warp    = threadIdx.x >> 5;
    const int lane    = threadIdx.x & 31;
    const int colBase = slab * TCOLS;

    float cs[8] = {0.f, 0.f, 0.f, 0.f, 0.f, 0.f, 0.f, 0.f};
    float f0=0.f, f1=0.f, f2=0.f, f3=0.f, a4=0.f, a5=0.f, a6=0.f, a7=0.f;
    int c00=0,c01=0,c02=0,c03=0,c04=0;
    int c10=0,c11=0,c12=0,c13=0,c14=0;
    int c20=0,c21=0,c22=0,c23=0,c24=0;
    int c30=0,c31=0,c32=0,c33=0,c34=0;

    for (int r = warp; r < TROWS; r += 8) {
        const int   row = rowBase + r;
        const float M   = g_rowM[row];
        const float inv = g_rowInv[row];
        const float4* p4 =
            reinterpret_cast<const float4*>(x + (size_t)row * C + colBase);
        float4 a = __ldg(p4 + lane);
        float4 b = __ldg(p4 + 32 + lane);
        float v[8] = {a.x, a.y, a.z, a.w, b.x, b.y, b.z, b.w};
        #pragma unroll
        for (int k = 0; k < 8; k++) {
            float p = __expf(v[k] - M) * inv;
            float t = (p - mnv) * invD;
            int idx = __float2int_rd(t);
            idx = max(idx, 0);                       // MUFU edge safety
            if (idx < NEMU) {
                int r0 = __float2int_rn(p * 32768.0f);
                int r1 = __float2int_rn(p * 16384.0f);
                int r2 = __float2int_rn(p * 8192.0f);
                int r3 = __float2int_rn(p * 4096.0f);
                int r4 = __float2int_rn(p * 2048.0f);
                if (idx == 0) {
                    f0 += p; c00+=r0; c01+=r1; c02+=r2; c03+=r3; c04+=r4;
                } else if (idx == 1) {
                    f1 += p; c10+=r0; c11+=r1; c12+=r2; c13+=r3; c14+=r4;
                } else if (idx == 2) {
                    f2 += p; c20+=r0; c21+=r1; c22+=r2; c23+=r3; c24+=r4;
                } else {
                    f3 += p; c30+=r0; c31+=r1; c32+=r2; c33+=r3; c34+=r4;
                }
            } else if (idx < NREG) {
                if (idx == 4)      a4 += p;
                else if (idx == 5) a5 += p;
                else if (idx == 6) a6 += p;
                else               a7 += p;
            } else if (idx < NBINS) {
                atomicAdd(&sh[idx], p);
            }                                        // idx >= 64: dropped
        }
        cs[0] += a.x; cs[1] += a.y; cs[2] += a.z; cs[3] += a.w;
        cs[4] += b.x; cs[5] += b.y; cs[6] += b.z; cs[7] += b.w;
    }

    #pragma unroll
    for (int k = 0; k < 4; k++) {
        scolW[warp][4 * lane + k]       = cs[k];
        scolW[warp][128 + 4 * lane + k] = cs[4 + k];
    }
    #pragma unroll
    for (int o = 16; o > 0; o >>= 1) {
        f0 += __shfl_xor_sync(0xffffffffu, f0, o);
        f1 += __shfl_xor_sync(0xffffffffu, f1, o);
        f2 += __shfl_xor_sync(0xffffffffu, f2, o);
        f3 += __shfl_xor_sync(0xffffffffu, f3, o);
        a4 += __shfl_xor_sync(0xffffffffu, a4, o);
        a5 += __shfl_xor_sync(0xffffffffu, a5, o);
        a6 += __shfl_xor_sync(0xffffffffu, a6, o);
        a7 += __shfl_xor_sync(0xffffffffu, a7, o);
        c00 += __shfl_xor_sync(0xffffffffu, c00, o);
        c01 += __shfl_xor_sync(0xffffffffu, c01, o);
        c02 += __shfl_xor_sync(0xffffffffu, c02, o);
        c03 += __shfl_xor_sync(0xffffffffu, c03, o);
        c04 += __shfl_xor_sync(0xffffffffu, c04, o);
        c10 += __shfl_xor_sync(0xffffffffu, c10, o);
        c11 += __shfl_xor_sync(0xffffffffu, c11, o);
        c12 += __shfl_xor_sync(0xffffffffu, c12, o);
        c13 += __shfl_xor_sync(0xffffffffu, c13, o);
        c14 += __shfl_xor_sync(0xffffffffu, c14, o);
        c20 += __shfl_xor_sync(0xffffffffu, c20, o);
        c21 += __shfl_xor_sync(0xffffffffu, c21, o);
        c22 += __shfl_xor_sync(0xffffffffu, c22, o);
        c23 += __shfl_xor_sync(0xffffffffu, c23, o);
        c24 += __shfl_xor_sync(0xffffffffu, c24, o);
        c30 += __shfl_xor_sync(0xffffffffu, c30, o);
        c31 += __shfl_xor_sync(0xffffffffu, c31, o);
        c32 += __shfl_xor_sync(0xffffffffu, c32, o);
        c33 += __shfl_xor_sync(0xffffffffu, c33, o);
        c34 += __shfl_xor_sync(0xffffffffu, c34, o);
    }
    if (lane == 0) {
        sFw[warp][0]=f0; sFw[warp][1]=f1; sFw[warp][2]=f2; sFw[warp][3]=f3;
        sFw[warp][4]=a4; sFw[warp][5]=a5; sFw[warp][6]=a6; sFw[warp][7]=a7;
        sIw[warp][0][0]=c00; sIw[warp][0][1]=c01; sIw[warp][0][2]=c02; sIw[warp][0][3]=c03; sIw[warp][0][4]=c04;
        sIw[warp][1][0]=c10; sIw[warp][1][1]=c11; sIw[warp][1][2]=c12; sIw[warp][1][3]=c13; sIw[warp][1][4]=c14;
        sIw[warp][2][0]=c20; sIw[warp][2][1]=c21; sIw[warp][2][2]=c22; sIw[warp][2][3]=c23; sIw[warp][2][4]=c24;
        sIw[warp][3][0]=c30; sIw[warp][3][1]=c31; sIw[warp][3][2]=c32; sIw[warp][3][3]=c33; sIw[warp][3][4]=c34;
    }
    __syncthreads();

    float csum = 0.0f;
    #pragma unroll
    for (int w = 0; w < 8; w++) csum += scolW[w][threadIdx.x];
    g_colPart[tile][colBase + threadIdx.x] = csum;

    const int chunk = tile * SLABS + slab;
    if (threadIdx.x < NEMU) {                        // thread b -> replay bin b
        const int b = threadIdx.x;
        float F = 0.f; int I0=0, I1=0, I2=0, I3=0, I4=0;
        #pragma unroll
        for (int w = 0; w < 8; w++) {
            F += sFw[w][b];
            I0 += sIw[w][b][0]; I1 += sIw[w][b][1]; I2 += sIw[w][b][2];
            I3 += sIw[w][b][3]; I4 += sIw[w][b][4];
        }
        g_bf[b][chunk] = F;
        g_bi[b][chunk][0] = I0; g_bi[b][chunk][1] = I1; g_bi[b][chunk][2] = I2;
        g_bi[b][chunk][3] = I3; g_bi[b][chunk][4] = I4;
    } else if (threadIdx.x < NREG) {                 // bins 4..7 from registers
        const int b = threadIdx.x;
        float F = 0.f;
        #pragma unroll
        for (int w = 0; w < 8; w++) F += sFw[w][b];
        g_histPart[chunk][b] = F;
    } else if (threadIdx.x < NBINS) {
        g_histPart[chunk][threadIdx.x] = sh[threadIdx.x];
    }
}

// ---------------------------------------------------------------------------
// Kernel 3: reduce hist partials for bins 4..63 (fixed tree)
// ---------------------------------------------------------------------------
__global__ __launch_bounds__(256) void histRedK(float* __restrict__ out) {
    const int bin = blockIdx.x + NEMU;               // bins 4..63
    float s = 0.0f;
    #pragma unroll
    for (int k = 0; k < NHB / 256; k++)
        s += g_histPart[threadIdx.x + k * 256][bin];
    __shared__ float sm[256];
    sm[threadIdx.x] = s;
    __syncthreads();
    #pragma unroll
    for (int st = 128; st > 0; st >>= 1) {
        if (threadIdx.x < st) sm[threadIdx.x] += sm[threadIdx.x + st];
        __syncthreads();
    }
    if (threadIdx.x == 0) out[C + bin] = sm[0];
}

// ---------------------------------------------------------------------------
// Kernel 4: serial fp32-accumulator replay, bins 0..3 (warp b -> bin b).
// Branchless regime select keeps the critical path = 1024 dependent DADDs.
// ---------------------------------------------------------------------------
__global__ void finalizeK(float* __restrict__ out) {
    const int w    = threadIdx.x >> 5;
    const int lane = threadIdx.x & 31;
    if (w >= NEMU) return;
    double A = 0.0;
    for (int b = 0; b < NHB / 32; b++) {
        const int c = b * 32 + lane;
        float fF = g_bf[w][c];
        int j0 = g_bi[w][c][0], j1 = g_bi[w][c][1], j2 = g_bi[w][c][2];
        int j3 = g_bi[w][c][3], j4 = g_bi[w][c][4];
        #pragma unroll
        for (int l = 0; l < 32; l++) {
            float ff = __shfl_sync(0xffffffffu, fF, l);
            int k0 = __shfl_sync(0xffffffffu, j0, l);
            int k1 = __shfl_sync(0xffffffffu, j1, l);
            int k2 = __shfl_sync(0xffffffffu, j2, l);
            int k3 = __shfl_sync(0xffffffffu, j3, l);
            int k4 = __shfl_sync(0xffffffffu, j4, l);
            double add =
                (A < 256.0)  ? (double)ff :
                (A < 512.0)  ? (double)k0 * (1.0 / 32768.0) :
                (A < 1024.0) ? (double)k1 * (1.0 / 16384.0) :
                (A < 2048.0) ? (double)k2 * (1.0 / 8192.0)  :
                (A < 4096.0) ? (double)k3 * (1.0 / 4096.0)  :
                               (double)k4 * (1.0 / 2048.0);
            A += add;
        }
    }
    if (lane == 0) out[C + w] = (float)A;
}

// ---------------------------------------------------------------------------
// Kernel 5: column means from 64 tile partials (fixed order), exact /8192
// ---------------------------------------------------------------------------
__global__ __launch_bounds__(256) void meanK(float* __restrict__ out) {
    const int c = blockIdx.x * 256 + threadIdx.x;
    float s = 0.0f;
    #pragma unroll
    for (int t = 0; t < RTILES; t++) s += g_colPart[t][c];
    out[c] = s * (1.0f / 8192.0f);
}

// ---------------------------------------------------------------------------
extern "C" void kernel_launch(void* const* d_in, const int* in_sizes, int n_in,
                              void* d_out, int out_size) {
    const float* x   = (const float*)d_in[0];   // seq [1, 8192, 4096]
    float*       out = (float*)d_out;           // [4160]

    initK    <<<1, 1>>>();
    rowK     <<<R, 256>>>(x);
    histColK <<<dim3(SLABS, RTILES), 256>>>(x);
    histRedK <<<NBINS - NEMU, 256>>>(out);
    finalizeK<<<1, NEMU * 32>>>(out);
    meanK    <<<C / 256, 256>>>(out);
}